// round 7
// baseline (speedup 1.0000x reference)
#include <cuda_runtime.h>
#include <cuda_bf16.h>
#include <math.h>
#include <stdint.h>

// Problem constants
constexpr int B_   = 256;
constexpr int L_   = 100;
constexpr int C_   = 55;
constexpr int D_   = 512;
constexpr int H_   = 8;
constexpr int NL_  = 3;
constexpr int DFF_ = 64;
constexpr int DK_  = D_ / H_;      // 64
constexpr int BL_  = B_ * L_;      // 25600
constexpr int KC_  = 3 * C_;       // 165
constexpr int KCP_ = 192;          // padded K for conv GEMM
constexpr int QS_  = 3 * D_;       // fused qkv row stride (1536)

// ---------------- scratch (static device allocations) ----------------------
__device__ float g_h   [BL_ * D_];
__device__ float g_qkv [BL_ * QS_];
__device__ float g_o   [BL_ * D_];
__device__ float g_y   [BL_ * DFF_];
__device__ float g_xg  [BL_ * KCP_];
__device__ float g_wp  [D_ * KCP_];
__device__ float g_wqkv[NL_ * QS_ * D_];
__device__ float g_bqkv[NL_ * QS_];

// ---------------- im2col gather (padded, zero-filled) -----------------------
__global__ void __launch_bounds__(256) gather_kernel(const float* __restrict__ x) {
    int idx = blockIdx.x * blockDim.x + threadIdx.x;
    const int total = BL_ * KCP_;
    if (idx >= total) return;
    int kk = idx % KCP_;
    int bl = idx / KCP_;
    float val = 0.f;
    if (kk < KC_) {
        int c = kk / 3, j = kk % 3;
        int b = bl / L_, l = bl % L_;
        int ls = l - 1 + j;
        if (ls < 0) ls += L_;
        if (ls >= L_) ls -= L_;
        val = x[((size_t)b * L_ + ls) * C_ + c];
    }
    g_xg[idx] = val;
}

__global__ void __launch_bounds__(256) packw_kernel(const float* __restrict__ w) {
    int idx = blockIdx.x * blockDim.x + threadIdx.x;
    const int total = D_ * KCP_;
    if (idx >= total) return;
    int kk = idx % KCP_;
    int r  = idx / KCP_;
    g_wp[idx] = (kk < KC_) ? w[(size_t)r * KC_ + kk] : 0.f;
}

// pack Wq/Wk/Wv -> [l][1536][512], bq/bk/bv -> [l][1536]
__global__ void __launch_bounds__(256) packqkv_kernel(
    const float* __restrict__ Wq, const float* __restrict__ Wk,
    const float* __restrict__ Wv,
    const float* __restrict__ bq, const float* __restrict__ bk,
    const float* __restrict__ bv)
{
    int idx = blockIdx.x * blockDim.x + threadIdx.x;
    const int perL = QS_ * D_;
    if (idx < NL_ * perL) {
        int l = idx / perL, rem = idx % perL;
        int row = rem / D_, col = rem % D_;
        const float* src = (row < D_) ? Wq : (row < 2 * D_) ? Wk : Wv;
        int r = row % D_;
        g_wqkv[idx] = src[((size_t)l * D_ + r) * D_ + col];
    }
    if (idx < NL_ * QS_) {
        int l = idx / QS_, row = idx % QS_;
        const float* src = (row < D_) ? bq : (row < 2 * D_) ? bk : bv;
        g_bqkv[idx] = src[(size_t)l * D_ + row % D_];
    }
}

// ---------------- bf16 hi/lo split helper -----------------------------------
__device__ __forceinline__ void split2(float x, float y,
                                       uint32_t& hi, uint32_t& lo) {
    __nv_bfloat16 hx = __float2bfloat16(x);
    __nv_bfloat16 hy = __float2bfloat16(y);
    float lx = x - __bfloat162float(hx);
    float ly = y - __bfloat162float(hy);
    __nv_bfloat16 gx = __float2bfloat16(lx);
    __nv_bfloat16 gy = __float2bfloat16(ly);
    hi = (uint32_t)__bfloat16_as_ushort(hx) |
         ((uint32_t)__bfloat16_as_ushort(hy) << 16);
    lo = (uint32_t)__bfloat16_as_ushort(gx) |
         ((uint32_t)__bfloat16_as_ushort(gy) << 16);
}

#define MMA_BF16(C, A0, A1, A2, A3, B0, B1)                                   \
    asm volatile(                                                             \
        "mma.sync.aligned.m16n8k16.row.col.f32.bf16.bf16.f32 "                \
        "{%0,%1,%2,%3}, {%4,%5,%6,%7}, {%8,%9}, {%0,%1,%2,%3};\n"             \
        : "+f"(C[0]), "+f"(C[1]), "+f"(C[2]), "+f"(C[3])                      \
        : "r"(A0), "r"(A1), "r"(A2), "r"(A3), "r"(B0), "r"(B1))

// ---------------- bf16x2-split tensor-core GEMM -----------------------------
// C [M,N] (+)= A[M,K] @ W[N,K]^T + bias, fp32 in/out, ~fp32 precision via
// hi/lo bf16 split (3 mma per K16).  MODE: 0 plain, 1 C+=, 2 GELU, 3 +PE.
// Requires M % 128 == 0, K % 32 == 0, 16B-aligned rows.
template<int BN, int MODE>
__global__ void __launch_bounds__(256, 1) mma_gemm(
    int M, int N, int K,
    const float* __restrict__ A,
    const float* __restrict__ W,
    const float* __restrict__ bias,
    float* __restrict__ Cp,
    const float* __restrict__ pe)
{
    constexpr int BM = 128, BK = 32;
    constexpr int WARPS_N = (BN == 128) ? 4 : 2;
    constexpr int WM = BM / (8 / WARPS_N);   // 64 or 32
    constexpr int WN = BN / WARPS_N;         // 32
    constexpr int MT = WM / 16;              // 4 or 2
    constexpr int NT = WN / 8;               // 4
    constexpr int STRW   = 20;               // uint32 words per row (40 bf16)
    constexpr int A_W    = BM * STRW;
    constexpr int B_W    = BN * STRW;
    constexpr int STAGE  = 2 * A_W + 2 * B_W;
    constexpr int ALOADS = BM * BK / 4 / 256;   // 4
    constexpr int BLOADS = BN * BK / 4 / 256;   // 4 or 2

    extern __shared__ uint32_t smw[];

    const int tid  = threadIdx.x;
    const int warp = tid >> 5, lane = tid & 31;
    const int wm = (warp / WARPS_N) * WM;
    const int wn = (warp % WARPS_N) * WN;
    const int g  = lane >> 2;
    const int tg = lane & 3;
    const int rowBase = blockIdx.y * BM;
    const int colBase = blockIdx.x * BN;

    float c[MT][NT][4];
    #pragma unroll
    for (int mt = 0; mt < MT; ++mt)
        #pragma unroll
        for (int nt = 0; nt < NT; ++nt)
            #pragma unroll
            for (int j = 0; j < 4; ++j) c[mt][nt][j] = 0.f;

    float4 aR[ALOADS], bR[BLOADS];

    auto loadG = [&](int k0) {
        #pragma unroll
        for (int i = 0; i < ALOADS; ++i) {
            int f = tid + i * 256;
            int r = f >> 3, cc = (f & 7) * 4;
            aR[i] = *reinterpret_cast<const float4*>(
                A + (size_t)(rowBase + r) * K + k0 + cc);
        }
        #pragma unroll
        for (int i = 0; i < BLOADS; ++i) {
            int f = tid + i * 256;
            int r = f >> 3, cc = (f & 7) * 4;
            int gr = colBase + r;
            bR[i] = (gr < N)
                ? *reinterpret_cast<const float4*>(W + (size_t)gr * K + k0 + cc)
                : make_float4(0.f, 0.f, 0.f, 0.f);
        }
    };

    auto storeS = [&](int s) {
        uint32_t* Ah = smw + s * STAGE;
        uint32_t* Al = Ah + A_W;
        uint32_t* Bh = Al + A_W;
        uint32_t* Bl = Bh + B_W;
        #pragma unroll
        for (int i = 0; i < ALOADS; ++i) {
            int f = tid + i * 256;
            int r = f >> 3, cw = (f & 7) * 2;
            uint32_t h0, l0, h1, l1;
            split2(aR[i].x, aR[i].y, h0, l0);
            split2(aR[i].z, aR[i].w, h1, l1);
            Ah[r * STRW + cw] = h0;  Ah[r * STRW + cw + 1] = h1;
            Al[r * STRW + cw] = l0;  Al[r * STRW + cw + 1] = l1;
        }
        #pragma unroll
        for (int i = 0; i < BLOADS; ++i) {
            int f = tid + i * 256;
            int r = f >> 3, cw = (f & 7) * 2;
            uint32_t h0, l0, h1, l1;
            split2(bR[i].x, bR[i].y, h0, l0);
            split2(bR[i].z, bR[i].w, h1, l1);
            Bh[r * STRW + cw] = h0;  Bh[r * STRW + cw + 1] = h1;
            Bl[r * STRW + cw] = l0;  Bl[r * STRW + cw + 1] = l1;
        }
    };

    auto compute = [&](int s) {
        const uint32_t* Ah = smw + s * STAGE;
        const uint32_t* Al = Ah + A_W;
        const uint32_t* Bh = Al + A_W;
        const uint32_t* Bl = Bh + B_W;
        #pragma unroll
        for (int ks = 0; ks < 2; ++ks) {
            const int base = ks * 8 + tg;
            uint32_t ah[MT][4], al[MT][4], bh[NT][2], bl[NT][2];
            #pragma unroll
            for (int mt = 0; mt < MT; ++mt) {
                int r0 = (wm + mt * 16 + g) * STRW;
                int r8 = r0 + 8 * STRW;
                ah[mt][0] = Ah[r0 + base];     ah[mt][1] = Ah[r8 + base];
                ah[mt][2] = Ah[r0 + base + 4]; ah[mt][3] = Ah[r8 + base + 4];
                al[mt][0] = Al[r0 + base];     al[mt][1] = Al[r8 + base];
                al[mt][2] = Al[r0 + base + 4]; al[mt][3] = Al[r8 + base + 4];
            }
            #pragma unroll
            for (int nt = 0; nt < NT; ++nt) {
                int n0 = (wn + nt * 8 + g) * STRW;
                bh[nt][0] = Bh[n0 + base]; bh[nt][1] = Bh[n0 + base + 4];
                bl[nt][0] = Bl[n0 + base]; bl[nt][1] = Bl[n0 + base + 4];
            }
            #pragma unroll
            for (int mt = 0; mt < MT; ++mt)
                #pragma unroll
                for (int nt = 0; nt < NT; ++nt) {
                    MMA_BF16(c[mt][nt], ah[mt][0], ah[mt][1], ah[mt][2],
                             ah[mt][3], bh[nt][0], bh[nt][1]);
                    MMA_BF16(c[mt][nt], ah[mt][0], ah[mt][1], ah[mt][2],
                             ah[mt][3], bl[nt][0], bl[nt][1]);
                    MMA_BF16(c[mt][nt], al[mt][0], al[mt][1], al[mt][2],
                             al[mt][3], bh[nt][0], bh[nt][1]);
                }
        }
    };

    const int nIter = K / BK;
    int s = 0;
    loadG(0);
    storeS(0);
    __syncthreads();
    for (int it = 0; it < nIter; ++it) {
        const bool more = (it + 1 < nIter);
        if (more) loadG((it + 1) * BK);
        compute(s);
        if (more) storeS(s ^ 1);
        __syncthreads();
        s ^= 1;
    }

    // epilogue
    #pragma unroll
    for (int mt = 0; mt < MT; ++mt) {
        #pragma unroll
        for (int nt = 0; nt < NT; ++nt) {
            int r0 = rowBase + wm + mt * 16 + g;
            int c0 = colBase + wn + nt * 8 + tg * 2;
            #pragma unroll
            for (int half = 0; half < 2; ++half) {
                int r = r0 + half * 8;
                #pragma unroll
                for (int jj = 0; jj < 2; ++jj) {
                    int cc = c0 + jj;
                    if (cc >= N) continue;
                    float v = c[mt][nt][half * 2 + jj];
                    if (bias) v += bias[cc];
                    if (MODE == 3) v += pe[(size_t)(r % L_) * N + cc];
                    if (MODE == 2) v = 0.5f * v * (1.f + erff(v * 0.70710678118654752f));
                    size_t off = (size_t)r * N + cc;
                    if (MODE == 1) v += Cp[off];
                    Cp[off] = v;
                }
            }
        }
    }
}

// ---------------- attention: one CTA per (b, h) -----------------------------
constexpr int S_STRIDE = 104;
constexpr int ATTN_SMEM_FLOATS = L_ * S_STRIDE + L_ * DK_ + DK_ * L_;
constexpr int ATTN_SMEM_BYTES  = ATTN_SMEM_FLOATS * 4;   // 92800 B

__global__ void __launch_bounds__(256) attn_kernel(
    const float* __restrict__ qkv,   // [BL][1536]: q|k|v
    float* __restrict__ o)           // [BL][512]
{
    extern __shared__ float sm[];
    float* S   = sm;                          // [100][104]
    float* qs  = sm + L_ * S_STRIDE;          // [100][64]
    float* kst = qs + L_ * DK_;               // [64][100] (reused for v)

    const int b = blockIdx.x / H_;
    const int h = blockIdx.x % H_;
    const float* qb = qkv + ((size_t)b * L_) * QS_ + h * DK_;
    const float* kb = qb + D_;
    const float* vb = qb + 2 * D_;
    float*       ob = o + ((size_t)b * L_) * D_ + h * DK_;
    const int tid = threadIdx.x;

    for (int idx = tid; idx < L_ * DK_; idx += blockDim.x) {
        int r = idx / DK_, e = idx % DK_;
        qs [r * DK_ + e] = qb[(size_t)r * QS_ + e];
        kst[e * L_  + r] = kb[(size_t)r * QS_ + e];
    }
    __syncthreads();

    const float scale = 0.125f;
    for (int p = tid; p < L_ * (L_ / 4); p += blockDim.x) {
        int i  = p / (L_ / 4);
        int j4 = (p % (L_ / 4)) * 4;
        float s0 = 0.f, s1 = 0.f, s2 = 0.f, s3 = 0.f;
        #pragma unroll 8
        for (int e = 0; e < DK_; ++e) {
            float qv = qs[i * DK_ + e];
            const float4 kv = *reinterpret_cast<const float4*>(kst + e * L_ + j4);
            s0 = fmaf(qv, kv.x, s0);
            s1 = fmaf(qv, kv.y, s1);
            s2 = fmaf(qv, kv.z, s2);
            s3 = fmaf(qv, kv.w, s3);
        }
        *reinterpret_cast<float4*>(S + i * S_STRIDE + j4) =
            make_float4(s0 * scale, s1 * scale, s2 * scale, s3 * scale);
    }
    __syncthreads();

    float* vs = kst;
    for (int idx = tid; idx < L_ * DK_; idx += blockDim.x) {
        int r = idx / DK_, e = idx % DK_;
        vs[r * DK_ + e] = vb[(size_t)r * QS_ + e];
    }
    {
        int warp = tid >> 5, lane = tid & 31;
        for (int i = warp; i < L_; i += (int)(blockDim.x >> 5)) {
            float* Sr = S + i * S_STRIDE;
            float m = -1e30f;
            for (int j = lane; j < L_; j += 32) m = fmaxf(m, Sr[j]);
            #pragma unroll
            for (int off = 16; off; off >>= 1)
                m = fmaxf(m, __shfl_xor_sync(0xffffffff, m, off));
            float sum = 0.f;
            for (int j = lane; j < L_; j += 32) {
                float ev = __expf(Sr[j] - m);
                Sr[j] = ev;
                sum += ev;
            }
            #pragma unroll
            for (int off = 16; off; off >>= 1)
                sum += __shfl_xor_sync(0xffffffff, sum, off);
            float inv = 1.f / sum;
            for (int j = lane; j < L_; j += 32) Sr[j] *= inv;
        }
    }
    __syncthreads();

    for (int idx = tid; idx < L_ * DK_; idx += blockDim.x) {
        int i = idx / DK_, d = idx % DK_;
        const float* Sr = S + i * S_STRIDE;
        float a0 = 0.f, a1 = 0.f, a2 = 0.f, a3 = 0.f;
        #pragma unroll 4
        for (int j = 0; j < L_; j += 4) {
            a0 = fmaf(Sr[j    ], vs[(j    ) * DK_ + d], a0);
            a1 = fmaf(Sr[j + 1], vs[(j + 1) * DK_ + d], a1);
            a2 = fmaf(Sr[j + 2], vs[(j + 2) * DK_ + d], a2);
            a3 = fmaf(Sr[j + 3], vs[(j + 3) * DK_ + d], a3);
        }
        ob[(size_t)i * D_ + d] = (a0 + a1) + (a2 + a3);
    }
}

// ---------------- host-side launch helper -----------------------------------
template<int BN, int MODE>
static void launch_one(const float* A, const float* W, const float* bias,
                       float* C, int M, int N, int K, const float* pe) {
    constexpr int STAGE_B = (2 * 128 * 20 + 2 * BN * 20) * 4;  // bytes/stage
    constexpr int SMEM = 2 * STAGE_B;
    static bool done = false;
    if (!done) {
        cudaFuncSetAttribute(mma_gemm<BN, MODE>,
                             cudaFuncAttributeMaxDynamicSharedMemorySize, SMEM);
        done = true;
    }
    dim3 grid((N + BN - 1) / BN, M / 128);
    mma_gemm<BN, MODE><<<grid, 256, SMEM>>>(M, N, K, A, W, bias, C, pe);
}

static void mgemm(const float* A, const float* W, const float* bias, float* C,
                  int M, int N, int K, int mode, const float* pe = nullptr) {
    if (N > 64) {
        switch (mode) {
            case 0: launch_one<128, 0>(A, W, bias, C, M, N, K, nullptr); break;
            case 1: launch_one<128, 1>(A, W, bias, C, M, N, K, nullptr); break;
            case 2: launch_one<128, 2>(A, W, bias, C, M, N, K, nullptr); break;
            default: launch_one<128, 3>(A, W, bias, C, M, N, K, pe);     break;
        }
    } else {
        switch (mode) {
            case 0: launch_one<64, 0>(A, W, bias, C, M, N, K, nullptr); break;
            case 1: launch_one<64, 1>(A, W, bias, C, M, N, K, nullptr); break;
            case 2: launch_one<64, 2>(A, W, bias, C, M, N, K, nullptr); break;
            default: launch_one<64, 3>(A, W, bias, C, M, N, K, pe);     break;
        }
    }
}

extern "C" void kernel_launch(void* const* d_in, const int* in_sizes, int n_in,
                              void* d_out, int out_size) {
    (void)in_sizes; (void)n_in; (void)out_size;
    const float* x     = (const float*)d_in[0];
    const float* tok_w = (const float*)d_in[1];
    const float* pe    = (const float*)d_in[2];
    const float* Wq    = (const float*)d_in[3];
    const float* bq    = (const float*)d_in[4];
    const float* Wk    = (const float*)d_in[5];
    const float* bk    = (const float*)d_in[6];
    const float* Wv    = (const float*)d_in[7];
    const float* bv    = (const float*)d_in[8];
    // d_in[9]/d_in[10] (Wsig/bsig): prior branch never reaches output -> skipped
    const float* Wo    = (const float*)d_in[11];
    const float* bo    = (const float*)d_in[12];
    const float* W1    = (const float*)d_in[13];
    const float* b1    = (const float*)d_in[14];
    const float* W2    = (const float*)d_in[15];
    const float* b2    = (const float*)d_in[16];
    const float* pw    = (const float*)d_in[17];
    const float* pb    = (const float*)d_in[18];
    float* out = (float*)d_out;

    float *h, *qkv, *o, *y, *xg, *wp, *wqkv, *bqkv;
    cudaGetSymbolAddress((void**)&h,    g_h);
    cudaGetSymbolAddress((void**)&qkv,  g_qkv);
    cudaGetSymbolAddress((void**)&o,    g_o);
    cudaGetSymbolAddress((void**)&y,    g_y);
    cudaGetSymbolAddress((void**)&xg,   g_xg);
    cudaGetSymbolAddress((void**)&wp,   g_wp);
    cudaGetSymbolAddress((void**)&wqkv, g_wqkv);
    cudaGetSymbolAddress((void**)&bqkv, g_bqkv);

    cudaFuncSetAttribute(attn_kernel,
                         cudaFuncAttributeMaxDynamicSharedMemorySize,
                         ATTN_SMEM_BYTES);

    // prep: padded im2col, padded tok_w, fused qkv weights
    gather_kernel<<<(BL_ * KCP_ + 255) / 256, 256>>>(x);
    packw_kernel<<<(D_ * KCP_ + 255) / 256, 256>>>(tok_w);
    packqkv_kernel<<<(NL_ * QS_ * D_ + 255) / 256, 256>>>(Wq, Wk, Wv, bq, bk, bv);

    // token embedding GEMM (+positional-embedding epilogue)
    mgemm(xg, wp, nullptr, h, BL_, D_, KCP_, 3, pe);

    for (int l = 0; l < NL_; ++l) {
        const size_t wOff = (size_t)l * D_ * D_;
        // fused QKV projection: [BL,512] @ [1536,512]^T
        mgemm(h, wqkv + (size_t)l * QS_ * D_, bqkv + (size_t)l * QS_,
              qkv, BL_, QS_, D_, 0);

        attn_kernel<<<B_ * H_, 256, ATTN_SMEM_BYTES>>>(qkv, o);

        mgemm(o, Wo + wOff, bo + (size_t)l * D_, h, BL_, D_, D_, 1);
        mgemm(h, W1 + (size_t)l * DFF_ * D_, b1 + (size_t)l * DFF_,
              y, BL_, DFF_, D_, 2);
        mgemm(y, W2 + (size_t)l * D_ * DFF_, b2 + (size_t)l * D_,
              h, BL_, D_, DFF_, 1);
    }

    mgemm(h, pw, pb, out, BL_, C_, D_, 0);
}

// round 9
// speedup vs baseline: 1.0111x; 1.0111x over previous
#include <cuda_runtime.h>
#include <cuda_bf16.h>
#include <math.h>
#include <stdint.h>

// Problem constants
constexpr int B_   = 256;
constexpr int L_   = 100;
constexpr int C_   = 55;
constexpr int D_   = 512;
constexpr int H_   = 8;
constexpr int NL_  = 3;
constexpr int DFF_ = 64;
constexpr int DK_  = D_ / H_;      // 64
constexpr int BL_  = B_ * L_;      // 25600
constexpr int KC_  = 3 * C_;       // 165
constexpr int KCP_ = 192;          // padded K for conv GEMM
constexpr int QS_  = 3 * D_;       // fused qkv row stride (1536)

// ---------------- scratch (static device allocations) ----------------------
__device__ float g_h   [BL_ * D_];
__device__ float g_qkv [BL_ * QS_];
__device__ float g_o   [BL_ * D_];
__device__ float g_y   [BL_ * DFF_];
__device__ float g_xg  [BL_ * KCP_];
__device__ float g_wp  [D_ * KCP_];
__device__ float g_wqkv[NL_ * QS_ * D_];
__device__ float g_bqkv[NL_ * QS_];

// ---------------- im2col gather (padded, zero-filled) -----------------------
__global__ void __launch_bounds__(256) gather_kernel(const float* __restrict__ x) {
    int idx = blockIdx.x * blockDim.x + threadIdx.x;
    const int total = BL_ * KCP_;
    if (idx >= total) return;
    int kk = idx % KCP_;
    int bl = idx / KCP_;
    float val = 0.f;
    if (kk < KC_) {
        int c = kk / 3, j = kk % 3;
        int b = bl / L_, l = bl % L_;
        int ls = l - 1 + j;
        if (ls < 0) ls += L_;
        if (ls >= L_) ls -= L_;
        val = x[((size_t)b * L_ + ls) * C_ + c];
    }
    g_xg[idx] = val;
}

__global__ void __launch_bounds__(256) packw_kernel(const float* __restrict__ w) {
    int idx = blockIdx.x * blockDim.x + threadIdx.x;
    const int total = D_ * KCP_;
    if (idx >= total) return;
    int kk = idx % KCP_;
    int r  = idx / KCP_;
    g_wp[idx] = (kk < KC_) ? w[(size_t)r * KC_ + kk] : 0.f;
}

// pack Wq/Wk/Wv -> [l][1536][512], bq/bk/bv -> [l][1536]
__global__ void __launch_bounds__(256) packqkv_kernel(
    const float* __restrict__ Wq, const float* __restrict__ Wk,
    const float* __restrict__ Wv,
    const float* __restrict__ bq, const float* __restrict__ bk,
    const float* __restrict__ bv)
{
    int idx = blockIdx.x * blockDim.x + threadIdx.x;
    const int perL = QS_ * D_;
    if (idx < NL_ * perL) {
        int l = idx / perL, rem = idx % perL;
        int row = rem / D_, col = rem % D_;
        const float* src = (row < D_) ? Wq : (row < 2 * D_) ? Wk : Wv;
        int r = row % D_;
        g_wqkv[idx] = src[((size_t)l * D_ + r) * D_ + col];
    }
    if (idx < NL_ * QS_) {
        int l = idx / QS_, row = idx % QS_;
        const float* src = (row < D_) ? bq : (row < 2 * D_) ? bk : bv;
        g_bqkv[idx] = src[(size_t)l * D_ + row % D_];
    }
}

// ---------------- bf16 hi/lo split helper -----------------------------------
__device__ __forceinline__ void split2(float x, float y,
                                       uint32_t& hi, uint32_t& lo) {
    __nv_bfloat16 hx = __float2bfloat16(x);
    __nv_bfloat16 hy = __float2bfloat16(y);
    float lx = x - __bfloat162float(hx);
    float ly = y - __bfloat162float(hy);
    __nv_bfloat16 gx = __float2bfloat16(lx);
    __nv_bfloat16 gy = __float2bfloat16(ly);
    hi = (uint32_t)__bfloat16_as_ushort(hx) |
         ((uint32_t)__bfloat16_as_ushort(hy) << 16);
    lo = (uint32_t)__bfloat16_as_ushort(gx) |
         ((uint32_t)__bfloat16_as_ushort(gy) << 16);
}

#define MMA_BF16(C, A0, A1, A2, A3, B0, B1)                                   \
    asm volatile(                                                             \
        "mma.sync.aligned.m16n8k16.row.col.f32.bf16.bf16.f32 "                \
        "{%0,%1,%2,%3}, {%4,%5,%6,%7}, {%8,%9}, {%0,%1,%2,%3};\n"             \
        : "+f"(C[0]), "+f"(C[1]), "+f"(C[2]), "+f"(C[3])                      \
        : "r"(A0), "r"(A1), "r"(A2), "r"(A3), "r"(B0), "r"(B1))

__device__ __forceinline__ void ldsm4(uint32_t& r0, uint32_t& r1,
                                      uint32_t& r2, uint32_t& r3,
                                      uint32_t addr) {
    asm volatile(
        "ldmatrix.sync.aligned.m8n8.x4.shared.b16 {%0,%1,%2,%3}, [%4];\n"
        : "=r"(r0), "=r"(r1), "=r"(r2), "=r"(r3) : "r"(addr));
}

// ---------------- bf16x2-split tensor-core GEMM (ldmatrix fragments) --------
// C [M,N] (+)= A[M,K] @ W[N,K]^T + bias, fp32 in/out, ~fp32 precision via
// hi/lo bf16 split (3 mma per k16).  MODE: 0 plain, 1 C+=, 2 GELU, 3 +PE.
// Requires M % 128 == 0, K % 32 == 0, 16B-aligned rows.
template<int BN, int MODE>
__global__ void __launch_bounds__(256, 1) mma_gemm(
    int M, int N, int K,
    const float* __restrict__ A,
    const float* __restrict__ W,
    const float* __restrict__ bias,
    float* __restrict__ Cp,
    const float* __restrict__ pe)
{
    constexpr int BM = 128, BK = 32;
    constexpr int WARPS_N = (BN == 128) ? 4 : 2;
    constexpr int WM = BM / (8 / WARPS_N);   // 64 or 32
    constexpr int WN = BN / WARPS_N;         // 32
    constexpr int MT  = WM / 16;             // 4 or 2
    constexpr int NT2 = WN / 16;             // 2 (16-wide n groups)
    constexpr int ROWB   = 80;               // bytes per plane row (32 bf16 + 8 pad)
    constexpr int STRW   = ROWB / 4;         // 20 words
    constexpr int A_BYTES = BM * ROWB;       // per plane
    constexpr int B_BYTES = BN * ROWB;
    constexpr int STAGE_B = 2 * A_BYTES + 2 * B_BYTES;
    constexpr int ALOADS = BM * BK / 4 / 256;   // 4
    constexpr int BLOADS = BN * BK / 4 / 256;   // 4 or 2

    extern __shared__ uint32_t smw[];
    const uint32_t smemBase = (uint32_t)__cvta_generic_to_shared(smw);

    const int tid  = threadIdx.x;
    const int warp = tid >> 5, lane = tid & 31;
    const int wm = (warp / WARPS_N) * WM;
    const int wn = (warp % WARPS_N) * WN;
    const int g  = lane >> 2;
    const int tg = lane & 3;
    const int rowBase = blockIdx.y * BM;
    const int colBase = blockIdx.x * BN;

    // ldmatrix lane-derived address components
    const int aRow = lane & 15;
    const int aKB  = (lane >> 4) * 16;
    const int bRow = (lane & 7) | (((lane >> 4) & 1) << 3);
    const int bKB  = ((lane >> 3) & 1) * 16;
    // base byte offsets within a stage for this lane's A/B tile rows
    const uint32_t aOff = (uint32_t)((wm + aRow) * ROWB + aKB);
    const uint32_t bOff = (uint32_t)((wn + bRow) * ROWB + bKB);

    float c[MT][2 * NT2][4];
    #pragma unroll
    for (int mt = 0; mt < MT; ++mt)
        #pragma unroll
        for (int nt = 0; nt < 2 * NT2; ++nt)
            #pragma unroll
            for (int j = 0; j < 4; ++j) c[mt][nt][j] = 0.f;

    float4 aR[ALOADS], bR[BLOADS];

    auto loadG = [&](int k0) {
        #pragma unroll
        for (int i = 0; i < ALOADS; ++i) {
            int f = tid + i * 256;
            int r = f >> 3, cc = (f & 7) * 4;
            aR[i] = *reinterpret_cast<const float4*>(
                A + (size_t)(rowBase + r) * K + k0 + cc);
        }
        #pragma unroll
        for (int i = 0; i < BLOADS; ++i) {
            int f = tid + i * 256;
            int r = f >> 3, cc = (f & 7) * 4;
            int gr = colBase + r;
            bR[i] = (gr < N)
                ? *reinterpret_cast<const float4*>(W + (size_t)gr * K + k0 + cc)
                : make_float4(0.f, 0.f, 0.f, 0.f);
        }
    };

    auto storeS = [&](int s) {
        uint32_t* base = smw + s * (STAGE_B / 4);
        uint32_t* Ah = base;
        uint32_t* Al = Ah + A_BYTES / 4;
        uint32_t* Bh = Al + A_BYTES / 4;
        uint32_t* Bl = Bh + B_BYTES / 4;
        #pragma unroll
        for (int i = 0; i < ALOADS; ++i) {
            int f = tid + i * 256;
            int r = f >> 3, cw = (f & 7) * 2;
            uint32_t h0, l0, h1, l1;
            split2(aR[i].x, aR[i].y, h0, l0);
            split2(aR[i].z, aR[i].w, h1, l1);
            *reinterpret_cast<uint2*>(&Ah[r * STRW + cw]) = make_uint2(h0, h1);
            *reinterpret_cast<uint2*>(&Al[r * STRW + cw]) = make_uint2(l0, l1);
        }
        #pragma unroll
        for (int i = 0; i < BLOADS; ++i) {
            int f = tid + i * 256;
            int r = f >> 3, cw = (f & 7) * 2;
            uint32_t h0, l0, h1, l1;
            split2(bR[i].x, bR[i].y, h0, l0);
            split2(bR[i].z, bR[i].w, h1, l1);
            *reinterpret_cast<uint2*>(&Bh[r * STRW + cw]) = make_uint2(h0, h1);
            *reinterpret_cast<uint2*>(&Bl[r * STRW + cw]) = make_uint2(l0, l1);
        }
    };

    auto compute = [&](int s) {
        const uint32_t stage = smemBase + (uint32_t)(s * STAGE_B);
        const uint32_t AhB = stage + aOff;
        const uint32_t AlB = AhB + A_BYTES;
        const uint32_t BhB = stage + 2 * A_BYTES + bOff;
        const uint32_t BlB = BhB + B_BYTES;
        #pragma unroll
        for (int ks = 0; ks < 2; ++ks) {
            const uint32_t kOfs = ks * 32;
            uint32_t ah[MT][4], al[MT][4], bh[NT2][4], bl[NT2][4];
            #pragma unroll
            for (int mt = 0; mt < MT; ++mt) {
                ldsm4(ah[mt][0], ah[mt][1], ah[mt][2], ah[mt][3],
                      AhB + mt * 16 * ROWB + kOfs);
                ldsm4(al[mt][0], al[mt][1], al[mt][2], al[mt][3],
                      AlB + mt * 16 * ROWB + kOfs);
            }
            #pragma unroll
            for (int n2 = 0; n2 < NT2; ++n2) {
                ldsm4(bh[n2][0], bh[n2][1], bh[n2][2], bh[n2][3],
                      BhB + n2 * 16 * ROWB + kOfs);
                ldsm4(bl[n2][0], bl[n2][1], bl[n2][2], bl[n2][3],
                      BlB + n2 * 16 * ROWB + kOfs);
            }
            #pragma unroll
            for (int mt = 0; mt < MT; ++mt)
                #pragma unroll
                for (int n2 = 0; n2 < NT2; ++n2)
                    #pragma unroll
                    for (int half = 0; half < 2; ++half) {
                        float* cc = c[mt][n2 * 2 + half];
                        uint32_t b0h = bh[n2][half * 2],
                                 b1h = bh[n2][half * 2 + 1];
                        uint32_t b0l = bl[n2][half * 2],
                                 b1l = bl[n2][half * 2 + 1];
                        MMA_BF16(cc, ah[mt][0], ah[mt][1], ah[mt][2],
                                 ah[mt][3], b0h, b1h);
                        MMA_BF16(cc, ah[mt][0], ah[mt][1], ah[mt][2],
                                 ah[mt][3], b0l, b1l);
                        MMA_BF16(cc, al[mt][0], al[mt][1], al[mt][2],
                                 al[mt][3], b0h, b1h);
                    }
        }
    };

    const int nIter = K / BK;
    int s = 0;
    loadG(0);
    storeS(0);
    __syncthreads();
    for (int it = 0; it < nIter; ++it) {
        const bool more = (it + 1 < nIter);
        if (more) loadG((it + 1) * BK);
        compute(s);
        if (more) storeS(s ^ 1);
        __syncthreads();
        s ^= 1;
    }

    // epilogue
    #pragma unroll
    for (int mt = 0; mt < MT; ++mt) {
        #pragma unroll
        for (int nt = 0; nt < 2 * NT2; ++nt) {
            int r0 = rowBase + wm + mt * 16 + g;
            int c0 = colBase + wn + nt * 8 + tg * 2;
            #pragma unroll
            for (int half = 0; half < 2; ++half) {
                int r = r0 + half * 8;
                #pragma unroll
                for (int jj = 0; jj < 2; ++jj) {
                    int cc = c0 + jj;
                    if (cc >= N) continue;
                    float v = c[mt][nt][half * 2 + jj];
                    if (bias) v += bias[cc];
                    if (MODE == 3) v += pe[(size_t)(r % L_) * N + cc];
                    if (MODE == 2) v = 0.5f * v * (1.f + erff(v * 0.70710678118654752f));
                    size_t off = (size_t)r * N + cc;
                    if (MODE == 1) v += Cp[off];
                    Cp[off] = v;
                }
            }
        }
    }
}

// ---------------- attention: one CTA per (b, h) -----------------------------
constexpr int S_STRIDE = 104;
constexpr int ATTN_SMEM_FLOATS = L_ * S_STRIDE + L_ * DK_ + DK_ * L_;
constexpr int ATTN_SMEM_BYTES  = ATTN_SMEM_FLOATS * 4;   // 92800 B

__global__ void __launch_bounds__(256) attn_kernel(
    const float* __restrict__ qkv,   // [BL][1536]: q|k|v
    float* __restrict__ o)           // [BL][512]
{
    extern __shared__ float sm[];
    float* S   = sm;                          // [100][104]
    float* qs  = sm + L_ * S_STRIDE;          // [100][64]
    float* kst = qs + L_ * DK_;               // [64][100] (reused for v)

    const int b = blockIdx.x / H_;
    const int h = blockIdx.x % H_;
    const float* qb = qkv + ((size_t)b * L_) * QS_ + h * DK_;
    const float* kb = qb + D_;
    const float* vb = qb + 2 * D_;
    float*       ob = o + ((size_t)b * L_) * D_ + h * DK_;
    const int tid = threadIdx.x;

    for (int idx = tid; idx < L_ * DK_; idx += blockDim.x) {
        int r = idx / DK_, e = idx % DK_;
        qs [r * DK_ + e] = qb[(size_t)r * QS_ + e];
        kst[e * L_  + r] = kb[(size_t)r * QS_ + e];
    }
    __syncthreads();

    const float scale = 0.125f;
    for (int p = tid; p < L_ * (L_ / 4); p += blockDim.x) {
        int i  = p / (L_ / 4);
        int j4 = (p % (L_ / 4)) * 4;
        float s0 = 0.f, s1 = 0.f, s2 = 0.f, s3 = 0.f;
        #pragma unroll 8
        for (int e = 0; e < DK_; ++e) {
            float qv = qs[i * DK_ + e];
            const float4 kv = *reinterpret_cast<const float4*>(kst + e * L_ + j4);
            s0 = fmaf(qv, kv.x, s0);
            s1 = fmaf(qv, kv.y, s1);
            s2 = fmaf(qv, kv.z, s2);
            s3 = fmaf(qv, kv.w, s3);
        }
        *reinterpret_cast<float4*>(S + i * S_STRIDE + j4) =
            make_float4(s0 * scale, s1 * scale, s2 * scale, s3 * scale);
    }
    __syncthreads();

    float* vs = kst;
    for (int idx = tid; idx < L_ * DK_; idx += blockDim.x) {
        int r = idx / DK_, e = idx % DK_;
        vs[r * DK_ + e] = vb[(size_t)r * QS_ + e];
    }
    {
        int warp = tid >> 5, lane = tid & 31;
        for (int i = warp; i < L_; i += (int)(blockDim.x >> 5)) {
            float* Sr = S + i * S_STRIDE;
            float m = -1e30f;
            for (int j = lane; j < L_; j += 32) m = fmaxf(m, Sr[j]);
            #pragma unroll
            for (int off = 16; off; off >>= 1)
                m = fmaxf(m, __shfl_xor_sync(0xffffffff, m, off));
            float sum = 0.f;
            for (int j = lane; j < L_; j += 32) {
                float ev = __expf(Sr[j] - m);
                Sr[j] = ev;
                sum += ev;
            }
            #pragma unroll
            for (int off = 16; off; off >>= 1)
                sum += __shfl_xor_sync(0xffffffff, sum, off);
            float inv = 1.f / sum;
            for (int j = lane; j < L_; j += 32) Sr[j] *= inv;
        }
    }
    __syncthreads();

    for (int idx = tid; idx < L_ * DK_; idx += blockDim.x) {
        int i = idx / DK_, d = idx % DK_;
        const float* Sr = S + i * S_STRIDE;
        float a0 = 0.f, a1 = 0.f, a2 = 0.f, a3 = 0.f;
        #pragma unroll 4
        for (int j = 0; j < L_; j += 4) {
            a0 = fmaf(Sr[j    ], vs[(j    ) * DK_ + d], a0);
            a1 = fmaf(Sr[j + 1], vs[(j + 1) * DK_ + d], a1);
            a2 = fmaf(Sr[j + 2], vs[(j + 2) * DK_ + d], a2);
            a3 = fmaf(Sr[j + 3], vs[(j + 3) * DK_ + d], a3);
        }
        ob[(size_t)i * D_ + d] = (a0 + a1) + (a2 + a3);
    }
}

// ---------------- host-side launch helper -----------------------------------
template<int BN, int MODE>
static void launch_one(const float* A, const float* W, const float* bias,
                       float* C, int M, int N, int K, const float* pe) {
    constexpr int STAGE_B = (2 * 128 + 2 * BN) * 80;  // bytes per stage
    constexpr int SMEM = 2 * STAGE_B;
    static bool done = false;
    if (!done) {
        cudaFuncSetAttribute(mma_gemm<BN, MODE>,
                             cudaFuncAttributeMaxDynamicSharedMemorySize, SMEM);
        done = true;
    }
    dim3 grid((N + BN - 1) / BN, M / 128);
    mma_gemm<BN, MODE><<<grid, 256, SMEM>>>(M, N, K, A, W, bias, C, pe);
}

static void mgemm(const float* A, const float* W, const float* bias, float* C,
                  int M, int N, int K, int mode, const float* pe = nullptr) {
    if (N > 64) {
        switch (mode) {
            case 0: launch_one<128, 0>(A, W, bias, C, M, N, K, nullptr); break;
            case 1: launch_one<128, 1>(A, W, bias, C, M, N, K, nullptr); break;
            case 2: launch_one<128, 2>(A, W, bias, C, M, N, K, nullptr); break;
            default: launch_one<128, 3>(A, W, bias, C, M, N, K, pe);     break;
        }
    } else {
        switch (mode) {
            case 0: launch_one<64, 0>(A, W, bias, C, M, N, K, nullptr); break;
            case 1: launch_one<64, 1>(A, W, bias, C, M, N, K, nullptr); break;
            case 2: launch_one<64, 2>(A, W, bias, C, M, N, K, nullptr); break;
            default: launch_one<64, 3>(A, W, bias, C, M, N, K, pe);     break;
        }
    }
}

extern "C" void kernel_launch(void* const* d_in, const int* in_sizes, int n_in,
                              void* d_out, int out_size) {
    (void)in_sizes; (void)n_in; (void)out_size;
    const float* x     = (const float*)d_in[0];
    const float* tok_w = (const float*)d_in[1];
    const float* pe    = (const float*)d_in[2];
    const float* Wq    = (const float*)d_in[3];
    const float* bq    = (const float*)d_in[4];
    const float* Wk    = (const float*)d_in[5];
    const float* bk    = (const float*)d_in[6];
    const float* Wv    = (const float*)d_in[7];
    const float* bv    = (const float*)d_in[8];
    // d_in[9]/d_in[10] (Wsig/bsig): prior branch never reaches output -> skipped
    const float* Wo    = (const float*)d_in[11];
    const float* bo    = (const float*)d_in[12];
    const float* W1    = (const float*)d_in[13];
    const float* b1    = (const float*)d_in[14];
    const float* W2    = (const float*)d_in[15];
    const float* b2    = (const float*)d_in[16];
    const float* pw    = (const float*)d_in[17];
    const float* pb    = (const float*)d_in[18];
    float* out = (float*)d_out;

    float *h, *qkv, *o, *y, *xg, *wp, *wqkv, *bqkv;
    cudaGetSymbolAddress((void**)&h,    g_h);
    cudaGetSymbolAddress((void**)&qkv,  g_qkv);
    cudaGetSymbolAddress((void**)&o,    g_o);
    cudaGetSymbolAddress((void**)&y,    g_y);
    cudaGetSymbolAddress((void**)&xg,   g_xg);
    cudaGetSymbolAddress((void**)&wp,   g_wp);
    cudaGetSymbolAddress((void**)&wqkv, g_wqkv);
    cudaGetSymbolAddress((void**)&bqkv, g_bqkv);

    cudaFuncSetAttribute(attn_kernel,
                         cudaFuncAttributeMaxDynamicSharedMemorySize,
                         ATTN_SMEM_BYTES);

    // prep: padded im2col, padded tok_w, fused qkv weights
    gather_kernel<<<(BL_ * KCP_ + 255) / 256, 256>>>(x);
    packw_kernel<<<(D_ * KCP_ + 255) / 256, 256>>>(tok_w);
    packqkv_kernel<<<(NL_ * QS_ * D_ + 255) / 256, 256>>>(Wq, Wk, Wv, bq, bk, bv);

    // token embedding GEMM (+positional-embedding epilogue)
    mgemm(xg, wp, nullptr, h, BL_, D_, KCP_, 3, pe);

    for (int l = 0; l < NL_; ++l) {
        const size_t wOff = (size_t)l * D_ * D_;
        // fused QKV projection: [BL,512] @ [1536,512]^T
        mgemm(h, wqkv + (size_t)l * QS_ * D_, bqkv + (size_t)l * QS_,
              qkv, BL_, QS_, D_, 0);

        attn_kernel<<<B_ * H_, 256, ATTN_SMEM_BYTES>>>(qkv, o);

        mgemm(o, Wo + wOff, bo + (size_t)l * D_, h, BL_, D_, D_, 1);
        mgemm(h, W1 + (size_t)l * DFF_ * D_, b1 + (size_t)l * DFF_,
              y, BL_, DFF_, D_, 2);
        mgemm(y, W2 + (size_t)l * D_ * DFF_, b2 + (size_t)l * D_,
              h, BL_, D_, DFF_, 1);
    }

    mgemm(h, pw, pb, out, BL_, C_, D_, 0);
}